// round 16
// baseline (speedup 1.0000x reference)
#include <cuda_runtime.h>
#include <cuda_fp16.h>
#include <stdint.h>
#include <math.h>

#define TT 2048     // tokens
#define HH 2048     // hidden
#define FF 1408     // moe intermediate
#define EE 60       // experts
#define TK 4        // top-k
#define SS 5632     // shared intermediate
#define NP (TT*TK)  // routed pairs

// ---- fp16 activations ----
__device__ __align__(16) __half g_xh[(size_t)TT*HH];
__device__ __align__(16) __half g_ybuf16[(size_t)TT*SS];
__device__ __align__(16) __half g_hbuf16[(size_t)NP*FF];
__device__ float g_pbuf[(size_t)NP*HH];
// ---- routing ----
__device__ float g_topw[NP];
__device__ int   g_topidx[NP];
__device__ float g_sig[TT];
__device__ int   g_off[EE+1];
__device__ int   g_tok[NP];
__device__ int   g_pos[NP];
__device__ int   g_ccnt[32][64];   // per-chunk expert histograms

// ============================ helpers ============================
__device__ __forceinline__ uint32_t smem_u32(const void* p) {
    uint32_t a;
    asm("{ .reg .u64 t; cvta.to.shared.u64 t, %1; cvt.u32.u64 %0, t; }" : "=r"(a) : "l"(p));
    return a;
}
__device__ __forceinline__ void ldsm4(uint32_t r[4], uint32_t addr) {
    asm volatile("ldmatrix.sync.aligned.m8n8.x4.shared.b16 {%0,%1,%2,%3}, [%4];"
        : "=r"(r[0]), "=r"(r[1]), "=r"(r[2]), "=r"(r[3]) : "r"(addr));
}
__device__ __forceinline__ void ldsm4t(uint32_t r[4], uint32_t addr) {
    asm volatile("ldmatrix.sync.aligned.m8n8.x4.trans.shared.b16 {%0,%1,%2,%3}, [%4];"
        : "=r"(r[0]), "=r"(r[1]), "=r"(r[2]), "=r"(r[3]) : "r"(addr));
}
__device__ __forceinline__ void mma_f16(float c[4], const uint32_t a[4], uint32_t b0, uint32_t b1) {
    asm volatile(
        "mma.sync.aligned.m16n8k16.row.col.f32.f16.f16.f32 "
        "{%0,%1,%2,%3}, {%4,%5,%6,%7}, {%8,%9}, {%0,%1,%2,%3};\n"
        : "+f"(c[0]), "+f"(c[1]), "+f"(c[2]), "+f"(c[3])
        : "r"(a[0]), "r"(a[1]), "r"(a[2]), "r"(a[3]), "r"(b0), "r"(b1));
}
__device__ __forceinline__ uint32_t pack_h2(__half a, __half b) {
    __half2 h = __halves2half2(a, b);
    return *(uint32_t*)&h;
}
__device__ __forceinline__ uint2 cvt4(uint4 v) {
    uint2 o;
    o.x = pack_h2(__float2half_rn(__uint_as_float(v.x)), __float2half_rn(__uint_as_float(v.y)));
    o.y = pack_h2(__float2half_rn(__uint_as_float(v.z)), __float2half_rn(__uint_as_float(v.w)));
    return o;
}
__device__ __forceinline__ float silu_f(float g) { return g / (1.f + __expf(-g)); }

#define CP16(d, s)  asm volatile("cp.async.cg.shared.global [%0], [%1], 16;" :: "r"(d), "l"(s))
#define CPCOMMIT()  asm volatile("cp.async.commit_group;" ::: "memory")
#define CPWAIT2()   asm volatile("cp.async.wait_group 2;" ::: "memory")

// ============================ router (fused x->fp16 emit, parallel logits) ============================
__global__ void router_kernel(const float* __restrict__ x,
                              const float* __restrict__ rw,
                              const float* __restrict__ seg)
{
    int t = blockIdx.x;
    int tid = threadIdx.x;              // 256 threads
    __shared__ float xs[HH];
    __shared__ float lg[EE];
    __shared__ float red[256];
    const float* xr = x + (size_t)t*HH;
    // load row + emit fp16 copy (coalesced 2B stores)
    for (int i = tid; i < HH; i += 256) {
        float v = xr[i];
        xs[i] = v;
        g_xh[(size_t)t*HH + i] = __float2half_rn(v);
    }
    __syncthreads();
    // logits: 4 threads per expert, each covers 512 k's
    {
        float p = 0.f;
        int e = tid >> 2;
        if (e < EE) {
            int k0 = (tid & 3) * 512;
            const float* rwp = rw + (size_t)k0*EE + e;
            #pragma unroll 4
            for (int k = 0; k < 512; k++)
                p = fmaf(xs[k0 + k], rwp[(size_t)k*EE], p);
        }
        p += __shfl_down_sync(0xffffffffu, p, 2);
        p += __shfl_down_sync(0xffffffffu, p, 1);
        if (e < EE && (tid & 3) == 0) lg[e] = p;
    }
    // sigmoid-gate dot
    {
        float p = 0.f;
        for (int k = tid; k < HH; k += 256) p = fmaf(xs[k], seg[k], p);
        red[tid] = p;
    }
    __syncthreads();
    if (tid == 0) {
        float m = lg[0];
        for (int e = 1; e < EE; e++) m = fmaxf(m, lg[e]);
        float s = 0.f;
        for (int e = 0; e < EE; e++) { float v = __expf(lg[e]-m); lg[e] = v; s += v; }
        float inv = 1.f/s;
        for (int e = 0; e < EE; e++) lg[e] *= inv;
        for (int j = 0; j < TK; j++) {
            int bi = 0; float bv = lg[0];
            for (int e = 1; e < EE; e++) { if (lg[e] > bv) { bv = lg[e]; bi = e; } }
            g_topidx[t*TK+j] = bi;
            g_topw[t*TK+j]  = bv;
            lg[bi] = -1.f;
        }
        float ss = 0.f;
        for (int i = 0; i < 256; i++) ss += red[i];
        g_sig[t] = 1.f/(1.f + __expf(-ss));
    }
}

// per-chunk histograms (32 chunks x 256 pairs)
__global__ void build2a_kernel()
{
    __shared__ int cnt[EE];
    int tid = threadIdx.x;              // 256
    if (tid < EE) cnt[tid] = 0;
    __syncthreads();
    atomicAdd(&cnt[g_topidx[blockIdx.x*256 + tid]], 1);
    __syncthreads();
    if (tid < EE) g_ccnt[blockIdx.x][tid] = cnt[tid];
}

// global offsets: per-expert totals in parallel, short serial prefix
__global__ void build1_kernel()
{
    __shared__ int tot[EE];
    int tid = threadIdx.x;              // 64
    if (tid < EE) {
        int s = 0;
        #pragma unroll
        for (int c = 0; c < 32; c++) s += g_ccnt[c][tid];
        tot[tid] = s;
    }
    __syncthreads();
    if (tid == 0) {
        int s = 0;
        for (int e = 0; e < EE; e++) { g_off[e] = s; s += tot[e]; }
        g_off[EE] = s;
    }
}

// deterministic rank: base from earlier chunks + within-chunk scan (<=255 iters)
__global__ void build2b_kernel()
{
    __shared__ int sidx[256];
    int tid = threadIdx.x;              // 256, grid 32
    int b = blockIdx.x;
    int p = b*256 + tid;
    int e = g_topidx[p];
    sidx[tid] = e;
    __syncthreads();
    int base = g_off[e];
    for (int c = 0; c < 32; c++) base += (c < b) ? g_ccnt[c][e] : 0;
    int r = 0;
    for (int q = 0; q < tid; q++) r += (sidx[q] == e);
    int pos = base + r;
    g_tok[pos] = p >> 2;
    g_pos[p]   = pos;
}

// ============================ pipeline layout ============================
// A fp16: 4 stages x TM*80B.  B fp32 staging: 3 stages x 17408B (32 rows x 544B).
// B fp16: 2 regions x 8704B (32 rows x 272B).
#define B32_ST 17408
#define F16_ST 8704

// ============================ fused gate+up GEMM (fp32 weights) ============================
template<bool MOE, int TM>
__global__ void __launch_bounds__(256,2) gemm_gateup(const float* __restrict__ Wg,
                                                     const float* __restrict__ Wu)
{
    constexpr int K = HH;
    constexpr int N = MOE ? FF : SS;
    constexpr int NSLAB = K/32;
    constexpr int NPB = (TM==128) ? 2 : 1;
    constexpr int A_ST = TM*80;
    constexpr int B32_OF = 4*A_ST;
    constexpr int F16_OF = B32_OF + 3*B32_ST;

    extern __shared__ __align__(16) char dsm[];
    const uint32_t sb = smem_u32(dsm);

    const int tid = threadIdx.x, lane = tid & 31, w = tid >> 5;
    const int wm  = (TM==128) ? (w & 3)*32 : (w & 1)*32;
    const int wn2 = (TM==128) ? (w >> 2)*32 : (w >> 1)*16;

    int e = 0, off = 0, cnt = TT;
    if (MOE) { e = blockIdx.z; off = g_off[e]; cnt = g_off[e+1] - off; }
    int mb;
    if (TM == 128) {
        mb = blockIdx.y*128;
        if (MOE && mb + 128 > cnt) return;
    } else {
        mb = (cnt & ~127) + blockIdx.y*64;
        if (mb >= cnt) return;
    }
    const int nb = blockIdx.x*64;   // per-matrix column tile

    const float* Bg = MOE ? Wg + (size_t)e*HH*FF : Wg;
    const float* Bu = MOE ? Wu + (size_t)e*HH*FF : Wu;

    // ---- A fill (fp16 cp.async) ----
    const int aseg = tid & 3, ar0 = tid >> 2;
    const __half *pa0, *pa1 = nullptr;
    if (MOE) {
        int rc0 = (mb+ar0 < cnt) ? (mb+ar0) : (cnt-1);
        pa0 = g_xh + (size_t)g_tok[off+rc0]*HH + aseg*8;
        if (TM == 128) {
            int rc1 = (mb+ar0+64 < cnt) ? (mb+ar0+64) : (cnt-1);
            pa1 = g_xh + (size_t)g_tok[off+rc1]*HH + aseg*8;
        }
    } else {
        pa0 = g_xh + (size_t)(mb+ar0)*K + aseg*8;
        pa1 = g_xh + (size_t)(mb+ar0+64)*K + aseg*8;
    }
    const uint32_t dA0 = (uint32_t)(ar0*80 + aseg*16);
    const uint32_t dA1 = (uint32_t)((ar0+64)*80 + aseg*16);

    // ---- B fp32 fill: rb = warp row base, c16 = 16B col group ----
    const int rb = tid >> 5, c16 = tid & 31;
    const float* pBbase = (((c16 & 16) ? Bu : Bg) + nb + (c16 & 15)*4) + (size_t)rb*N;
    uint32_t dBB[4], dFF[4];
    #pragma unroll
    for (int k = 0; k < 4; k++) {
        dBB[k] = (uint32_t)((rb + 8*k)*544 + c16*16);
        dFF[k] = (uint32_t)((rb + 8*k)*272 + c16*8);
    }

    // ---- fragment addresses ----
    const int lr = lane & 15, lc = lane >> 4;
    const uint32_t aoff0 = (uint32_t)((wm + lr)*80 + lc*16);
    const uint32_t aoff1 = aoff0 + 16*80;
    uint32_t bG[NPB], bU[NPB];
    #pragma unroll
    for (int np = 0; np < NPB; np++) {
        bG[np] = (uint32_t)(lr*272 + (wn2 + np*16 + lc*8)*2);
        bU[np] = bG[np] + 128;
    }

    float accG[2][2*NPB][4] = {}, accU[2][2*NPB][4] = {};

    // ---- prologue: stages 0,1,2 (A + B fp32), one commit each ----
    #pragma unroll
    for (int s = 0; s < 3; s++) {
        uint32_t ab = sb + s*A_ST;
        CP16(ab + dA0, pa0 + s*32);
        if (TM == 128) CP16(ab + dA1, pa1 + s*32);
        uint32_t bbs = sb + B32_OF + s*B32_ST;
        #pragma unroll
        for (int k = 0; k < 4; k++) CP16(bbs + dBB[k], pBbase + (size_t)(8*k)*N + (size_t)s*32*N);
        CPCOMMIT();
    }

    for (int i = 0; i < NSLAB; i++) {
        CPWAIT2();          // stage i (A + B32) complete
        {
            const char* bsm = dsm + B32_OF + (i%3)*B32_ST;
            uint4 v0 = *(const uint4*)(bsm + dBB[0]);
            uint4 v1 = *(const uint4*)(bsm + dBB[1]);
            uint4 v2 = *(const uint4*)(bsm + dBB[2]);
            uint4 v3 = *(const uint4*)(bsm + dBB[3]);
            char* fsm = dsm + F16_OF + (i&1)*F16_ST;
            *(uint2*)(fsm + dFF[0]) = cvt4(v0);
            *(uint2*)(fsm + dFF[1]) = cvt4(v1);
            *(uint2*)(fsm + dFF[2]) = cvt4(v2);
            *(uint2*)(fsm + dFF[3]) = cvt4(v3);
        }
        __syncthreads();    // publish F16_i; all readers of reused regions done
        if (i + 3 < NSLAB) {
            uint32_t ab = sb + ((i+3)&3)*A_ST;
            CP16(ab + dA0, pa0 + (i+3)*32);
            if (TM == 128) CP16(ab + dA1, pa1 + (i+3)*32);
            uint32_t bbs = sb + B32_OF + ((i+3)%3)*B32_ST;
            #pragma unroll
            for (int k = 0; k < 4; k++) CP16(bbs + dBB[k], pBbase + (size_t)(8*k)*N + (size_t)(i+3)*32*N);
        }
        CPCOMMIT();         // unconditional: keeps group count aligned in tail
        const uint32_t ab = sb + (uint32_t)((i&3)*A_ST);
        const uint32_t fbm = sb + F16_OF + (uint32_t)((i&1)*F16_ST);
        #pragma unroll
        for (int ks = 0; ks < 2; ks++) {
            uint32_t a0[4], a1[4];
            ldsm4(a0, ab + aoff0 + ks*32);
            ldsm4(a1, ab + aoff1 + ks*32);
            #pragma unroll
            for (int np = 0; np < NPB; np++) {
                uint32_t gg[4], uu[4];
                ldsm4t(gg, fbm + bG[np] + ks*16*272);
                ldsm4t(uu, fbm + bU[np] + ks*16*272);
                mma_f16(accG[0][2*np],   a0, gg[0], gg[1]);
                mma_f16(accG[0][2*np+1], a0, gg[2], gg[3]);
                mma_f16(accG[1][2*np],   a1, gg[0], gg[1]);
                mma_f16(accG[1][2*np+1], a1, gg[2], gg[3]);
                mma_f16(accU[0][2*np],   a0, uu[0], uu[1]);
                mma_f16(accU[0][2*np+1], a0, uu[2], uu[3]);
                mma_f16(accU[1][2*np],   a1, uu[0], uu[1]);
                mma_f16(accU[1][2*np+1], a1, uu[2], uu[3]);
            }
        }
    }

    __half* dst = MOE ? g_hbuf16 : g_ybuf16;
    #pragma unroll
    for (int mt = 0; mt < 2; mt++) {
        const int rl0 = mb + wm + mt*16 + (lane >> 2);
        const int rl1 = rl0 + 8;
        const bool v0 = MOE ? (rl0 < cnt) : true;
        const bool v1 = MOE ? (rl1 < cnt) : true;
        const size_t row0 = MOE ? (size_t)(off + rl0) : (size_t)rl0;
        const size_t row1 = MOE ? (size_t)(off + rl1) : (size_t)rl1;
        #pragma unroll
        for (int nt = 0; nt < 2*NPB; nt++) {
            const int col = nb + wn2 + nt*8 + (lane & 3)*2;
            const float* g = accG[mt][nt];
            const float* u = accU[mt][nt];
            if (v0) *(__half2*)&dst[row0*N + col] =
                __floats2half2_rn(silu_f(g[0])*u[0], silu_f(g[1])*u[1]);
            if (v1) *(__half2*)&dst[row1*N + col] =
                __floats2half2_rn(silu_f(g[2])*u[2], silu_f(g[3])*u[3]);
        }
    }
}

// ============================ down GEMM (fp32 weights) ============================
template<bool MOE, int TM>
__global__ void __launch_bounds__(256,2) gemm_down(const float* __restrict__ Wd,
                                                   float* __restrict__ Cex)
{
    constexpr int K = MOE ? FF : SS;
    constexpr int N = HH;
    constexpr int NSLAB = K/32;
    constexpr int NPW = (TM==128) ? 4 : 2;
    constexpr int A_ST = TM*80;
    constexpr int B32_OF = 4*A_ST;
    constexpr int F16_OF = B32_OF + 3*B32_ST;

    extern __shared__ __align__(16) char dsm[];
    const uint32_t sb = smem_u32(dsm);

    const int tid = threadIdx.x, lane = tid & 31, w = tid >> 5;
    const int wm = (TM==128) ? (w & 3)*32 : (w & 1)*32;
    const int wn = (TM==128) ? (w >> 2)*64 : (w >> 1)*32;

    int e = 0, off = 0, cnt = TT;
    if (MOE) { e = blockIdx.z; off = g_off[e]; cnt = g_off[e+1] - off; }
    int mb;
    if (TM == 128) {
        mb = blockIdx.y*128;
        if (MOE && mb + 128 > cnt) return;
    } else {
        mb = (cnt & ~127) + blockIdx.y*64;
        if (mb >= cnt) return;
    }
    const int nb = blockIdx.x*128;

    const float* Bp = MOE ? Wd + (size_t)e*FF*HH : Wd;

    // ---- A fill ----
    const int aseg = tid & 3, ar0 = tid >> 2;
    const __half *pa0, *pa1 = nullptr;
    if (MOE) {
        int rc0 = (mb+ar0 < cnt) ? (mb+ar0) : (cnt-1);
        pa0 = g_hbuf16 + (size_t)(off+rc0)*FF + aseg*8;
        if (TM == 128) {
            int rc1 = (mb+ar0+64 < cnt) ? (mb+ar0+64) : (cnt-1);
            pa1 = g_hbuf16 + (size_t)(off+rc1)*FF + aseg*8;
        }
    } else {
        pa0 = g_ybuf16 + (size_t)(mb+ar0)*K + aseg*8;
        pa1 = g_ybuf16 + (size_t)(mb+ar0+64)*K + aseg*8;
    }
    const uint32_t dA0 = (uint32_t)(ar0*80 + aseg*16);
    const uint32_t dA1 = (uint32_t)((ar0+64)*80 + aseg*16);

    // ---- B fp32 fill ----
    const int rb = tid >> 5, c16 = tid & 31;
    const float* pBbase = (Bp + nb + c16*4) + (size_t)rb*N;
    uint32_t dBB[4], dFF[4];
    #pragma unroll
    for (int k = 0; k < 4; k++) {
        dBB[k] = (uint32_t)((rb + 8*k)*544 + c16*16);
        dFF[k] = (uint32_t)((rb + 8*k)*272 + c16*8);
    }

    // ---- fragment addresses ----
    const int lr = lane & 15, lc = lane >> 4;
    const uint32_t aoff0 = (uint32_t)((wm + lr)*80 + lc*16);
    const uint32_t aoff1 = aoff0 + 16*80;
    uint32_t boff[NPW];
    #pragma unroll
    for (int np = 0; np < NPW; np++)
        boff[np] = (uint32_t)(lr*272 + (wn + np*16 + lc*8)*2);

    float acc[2][2*NPW][4] = {};

    // ---- prologue ----
    #pragma unroll
    for (int s = 0; s < 3; s++) {
        uint32_t ab = sb + s*A_ST;
        CP16(ab + dA0, pa0 + s*32);
        if (TM == 128) CP16(ab + dA1, pa1 + s*32);
        uint32_t bbs = sb + B32_OF + s*B32_ST;
        #pragma unroll
        for (int k = 0; k < 4; k++) CP16(bbs + dBB[k], pBbase + (size_t)(8*k)*N + (size_t)s*32*N);
        CPCOMMIT();
    }

    for (int i = 0; i < NSLAB; i++) {
        CPWAIT2();
        {
            const char* bsm = dsm + B32_OF + (i%3)*B32_ST;
            uint4 v0 = *(const uint4*)(bsm + dBB[0]);
            uint4 v1 = *(const uint4*)(bsm + dBB[1]);
            uint4 v2 = *(const uint4*)(bsm + dBB[2]);
            uint4 v3 = *(const uint4*)(bsm + dBB[3]);
            char* fsm = dsm + F16_OF + (i&1)*F16_ST;
            *(uint2*)(fsm + dFF[0]) = cvt4(v0);
            *(uint2*)(fsm + dFF[1]) = cvt4(v1);
            *(uint2*)(fsm + dFF[2]) = cvt4(v2);
            *(uint2*)(fsm + dFF[3]) = cvt4(v3);
        }
        __syncthreads();
        if (i + 3 < NSLAB) {
            uint32_t ab = sb + ((i+3)&3)*A_ST;
            CP16(ab + dA0, pa0 + (i+3)*32);
            if (TM == 128) CP16(ab + dA1, pa1 + (i+3)*32);
            uint32_t bbs = sb + B32_OF + ((i+3)%3)*B32_ST;
            #pragma unroll
            for (int k = 0; k < 4; k++) CP16(bbs + dBB[k], pBbase + (size_t)(8*k)*N + (size_t)(i+3)*32*N);
        }
        CPCOMMIT();
        const uint32_t ab = sb + (uint32_t)((i&3)*A_ST);
        const uint32_t fbm = sb + F16_OF + (uint32_t)((i&1)*F16_ST);
        #pragma unroll
        for (int ks = 0; ks < 2; ks++) {
            uint32_t a0[4], a1[4];
            ldsm4(a0, ab + aoff0 + ks*32);
            ldsm4(a1, ab + aoff1 + ks*32);
            #pragma unroll
            for (int np = 0; np < NPW; np++) {
                uint32_t bbr[4];
                ldsm4t(bbr, fbm + boff[np] + ks*16*272);
                mma_f16(acc[0][2*np],   a0, bbr[0], bbr[1]);
                mma_f16(acc[0][2*np+1], a0, bbr[2], bbr[3]);
                mma_f16(acc[1][2*np],   a1, bbr[0], bbr[1]);
                mma_f16(acc[1][2*np+1], a1, bbr[2], bbr[3]);
            }
        }
    }

    #pragma unroll
    for (int mt = 0; mt < 2; mt++) {
        const int rl0 = mb + wm + mt*16 + (lane >> 2);
        const int rl1 = rl0 + 8;
        const bool v0 = MOE ? (rl0 < cnt) : true;
        const bool v1 = MOE ? (rl1 < cnt) : true;
        #pragma unroll
        for (int nt = 0; nt < 2*NPW; nt++) {
            const int col = nb + wn + nt*8 + (lane & 3)*2;
            const float* c = acc[mt][nt];
            if (!MOE) {
                float s0 = g_sig[rl0], s1 = g_sig[rl1];
                *(float2*)&Cex[(size_t)rl0*HH + col] = make_float2(s0*c[0], s0*c[1]);
                *(float2*)&Cex[(size_t)rl1*HH + col] = make_float2(s1*c[2], s1*c[3]);
            } else {
                if (v0) *(float2*)&g_pbuf[(size_t)(off+rl0)*HH + col] = make_float2(c[0], c[1]);
                if (v1) *(float2*)&g_pbuf[(size_t)(off+rl1)*HH + col] = make_float2(c[2], c[3]);
            }
        }
    }
}

// ============================ combine ============================
__global__ void combine_kernel(float* __restrict__ out)
{
    int t = blockIdx.x, tid = threadIdx.x;
    int p0 = g_pos[t*4+0], p1 = g_pos[t*4+1], p2 = g_pos[t*4+2], p3 = g_pos[t*4+3];
    float w0 = g_topw[t*4+0], w1 = g_topw[t*4+1], w2 = g_topw[t*4+2], w3 = g_topw[t*4+3];
    const float* r0 = g_pbuf + (size_t)p0*HH;
    const float* r1 = g_pbuf + (size_t)p1*HH;
    const float* r2 = g_pbuf + (size_t)p2*HH;
    const float* r3 = g_pbuf + (size_t)p3*HH;
    for (int c = tid; c < HH; c += 256) {
        float v = out[(size_t)t*HH + c];
        v = fmaf(w0, r0[c], v);
        v = fmaf(w1, r1[c], v);
        v = fmaf(w2, r2[c], v);
        v = fmaf(w3, r3[c], v);
        out[(size_t)t*HH + c] = v;
    }
}

// ============================ launch ============================
#define SM128 (4*(128*80) + 3*B32_ST + 2*F16_ST)   // 110592
#define SM64  (4*(64*80)  + 3*B32_ST + 2*F16_ST)   // 90112

extern "C" void kernel_launch(void* const* d_in, const int* in_sizes, int n_in,
                              void* d_out, int out_size)
{
    const float* x   = (const float*)d_in[0];
    const float* rw  = (const float*)d_in[1];
    const float* wg  = (const float*)d_in[2];
    const float* wu  = (const float*)d_in[3];
    const float* wd  = (const float*)d_in[4];
    const float* shg = (const float*)d_in[5];
    const float* shu = (const float*)d_in[6];
    const float* shd = (const float*)d_in[7];
    const float* seg = (const float*)d_in[8];
    float* out = (float*)d_out;
    (void)in_sizes; (void)n_in; (void)out_size;

    static bool init = false;
    if (!init) {
        init = true;
        cudaFuncSetAttribute(gemm_gateup<false,128>, cudaFuncAttributeMaxDynamicSharedMemorySize, SM128);
        cudaFuncSetAttribute(gemm_gateup<true,128>,  cudaFuncAttributeMaxDynamicSharedMemorySize, SM128);
        cudaFuncSetAttribute(gemm_gateup<true,64>,   cudaFuncAttributeMaxDynamicSharedMemorySize, SM64);
        cudaFuncSetAttribute(gemm_down<false,128>,   cudaFuncAttributeMaxDynamicSharedMemorySize, SM128);
        cudaFuncSetAttribute(gemm_down<true,128>,    cudaFuncAttributeMaxDynamicSharedMemorySize, SM128);
        cudaFuncSetAttribute(gemm_down<true,64>,     cudaFuncAttributeMaxDynamicSharedMemorySize, SM64);
    }

    // ---- routing (router also emits g_xh fp16) ----
    router_kernel<<<TT, 256>>>(x, rw, seg);
    build2a_kernel<<<32, 256>>>();
    build1_kernel<<<1, 64>>>();
    build2b_kernel<<<32, 256>>>();

    // ---- shared expert ----
    gemm_gateup<false,128><<<dim3(SS/64, TT/128), 256, SM128>>>(shg, shu);
    gemm_down<false,128><<<dim3(HH/128, TT/128), 256, SM128>>>(shd, out);

    // ---- MoE: full 128-row tiles + 64-row tails ----
    gemm_gateup<true,128><<<dim3(FF/64, TT/128, EE), 256, SM128>>>(wg, wu);
    gemm_gateup<true,64> <<<dim3(FF/64, 2, EE),      256, SM64 >>>(wg, wu);
    gemm_down<true,128><<<dim3(HH/128, TT/128, EE), 256, SM128>>>(wd, nullptr);
    gemm_down<true,64> <<<dim3(HH/128, 2, EE),      256, SM64 >>>(wd, nullptr);

    combine_kernel<<<TT, 256>>>(out);
}

// round 17
// speedup vs baseline: 1.0717x; 1.0717x over previous
#include <cuda_runtime.h>
#include <cuda_fp16.h>
#include <stdint.h>
#include <math.h>

#define TT 2048     // tokens
#define HH 2048     // hidden
#define FF 1408     // moe intermediate
#define EE 60       // experts
#define TK 4        // top-k
#define SS 5632     // shared intermediate
#define NP (TT*TK)  // routed pairs

// ---- fp16 activations ----
__device__ __align__(16) __half g_xh[(size_t)TT*HH];
__device__ __align__(16) __half g_ybuf16[(size_t)TT*SS];
__device__ __align__(16) __half g_hbuf16[(size_t)NP*FF];
__device__ float g_pbuf[(size_t)NP*HH];
// ---- routing ----
__device__ float g_topw[NP];
__device__ int   g_topidx[NP];
__device__ float g_sig[TT];
__device__ int   g_off[EE+1];
__device__ int   g_tok[NP];
__device__ int   g_pos[NP];
__device__ int   g_ccnt[32][64];   // per-chunk expert histograms

// ============================ helpers ============================
__device__ __forceinline__ uint32_t smem_u32(const void* p) {
    uint32_t a;
    asm("{ .reg .u64 t; cvta.to.shared.u64 t, %1; cvt.u32.u64 %0, t; }" : "=r"(a) : "l"(p));
    return a;
}
__device__ __forceinline__ void ldsm4(uint32_t r[4], uint32_t addr) {
    asm volatile("ldmatrix.sync.aligned.m8n8.x4.shared.b16 {%0,%1,%2,%3}, [%4];"
        : "=r"(r[0]), "=r"(r[1]), "=r"(r[2]), "=r"(r[3]) : "r"(addr));
}
__device__ __forceinline__ void ldsm4t(uint32_t r[4], uint32_t addr) {
    asm volatile("ldmatrix.sync.aligned.m8n8.x4.trans.shared.b16 {%0,%1,%2,%3}, [%4];"
        : "=r"(r[0]), "=r"(r[1]), "=r"(r[2]), "=r"(r[3]) : "r"(addr));
}
__device__ __forceinline__ void mma_f16(float c[4], const uint32_t a[4], uint32_t b0, uint32_t b1) {
    asm volatile(
        "mma.sync.aligned.m16n8k16.row.col.f32.f16.f16.f32 "
        "{%0,%1,%2,%3}, {%4,%5,%6,%7}, {%8,%9}, {%0,%1,%2,%3};\n"
        : "+f"(c[0]), "+f"(c[1]), "+f"(c[2]), "+f"(c[3])
        : "r"(a[0]), "r"(a[1]), "r"(a[2]), "r"(a[3]), "r"(b0), "r"(b1));
}
__device__ __forceinline__ uint32_t pack_h2(__half a, __half b) {
    __half2 h = __halves2half2(a, b);
    return *(uint32_t*)&h;
}
__device__ __forceinline__ uint2 cvt4(uint4 v) {
    uint2 o;
    o.x = pack_h2(__float2half_rn(__uint_as_float(v.x)), __float2half_rn(__uint_as_float(v.y)));
    o.y = pack_h2(__float2half_rn(__uint_as_float(v.z)), __float2half_rn(__uint_as_float(v.w)));
    return o;
}
__device__ __forceinline__ float silu_f(float g) { return g / (1.f + __expf(-g)); }

#define CP16(d, s)  asm volatile("cp.async.cg.shared.global [%0], [%1], 16;" :: "r"(d), "l"(s))
#define CPCOMMIT()  asm volatile("cp.async.commit_group;" ::: "memory")
#define CPWAIT2()   asm volatile("cp.async.wait_group 2;" ::: "memory")

// ============================ router (R15 layout; fused x->fp16 emit) ============================
__global__ void router_kernel(const float* __restrict__ x,
                              const float* __restrict__ rw,
                              const float* __restrict__ seg)
{
    int t = blockIdx.x;
    int tid = threadIdx.x;              // 64 threads
    __shared__ float xs[HH];
    __shared__ float lg[EE];
    __shared__ float red[64];
    const float* xr = x + (size_t)t*HH;
    for (int i = tid; i < HH; i += 64) {
        float v = xr[i];
        xs[i] = v;
        g_xh[(size_t)t*HH + i] = __float2half_rn(v);
    }
    __syncthreads();
    if (tid < EE) {
        float a=0.f,b=0.f,c=0.f,d=0.f;
        for (int k = 0; k < HH; k += 4) {
            a = fmaf(xs[k+0], rw[(size_t)(k+0)*EE + tid], a);
            b = fmaf(xs[k+1], rw[(size_t)(k+1)*EE + tid], b);
            c = fmaf(xs[k+2], rw[(size_t)(k+2)*EE + tid], c);
            d = fmaf(xs[k+3], rw[(size_t)(k+3)*EE + tid], d);
        }
        lg[tid] = (a+b)+(c+d);
    }
    float p = 0.f;
    for (int k = tid; k < HH; k += 64) p = fmaf(xs[k], seg[k], p);
    red[tid] = p;
    __syncthreads();
    if (tid == 0) {
        float m = lg[0];
        for (int e = 1; e < EE; e++) m = fmaxf(m, lg[e]);
        float s = 0.f;
        for (int e = 0; e < EE; e++) { float v = __expf(lg[e]-m); lg[e] = v; s += v; }
        float inv = 1.f/s;
        for (int e = 0; e < EE; e++) lg[e] *= inv;
        for (int j = 0; j < TK; j++) {
            int bi = 0; float bv = lg[0];
            for (int e = 1; e < EE; e++) { if (lg[e] > bv) { bv = lg[e]; bi = e; } }
            g_topidx[t*TK+j] = bi;
            g_topw[t*TK+j]  = bv;
            lg[bi] = -1.f;
        }
        float ss = 0.f;
        for (int i = 0; i < 64; i++) ss += red[i];
        g_sig[t] = 1.f/(1.f + __expf(-ss));
    }
}

// per-chunk histograms (32 chunks x 256 pairs)
__global__ void build2a_kernel()
{
    __shared__ int cnt[EE];
    int tid = threadIdx.x;              // 256
    if (tid < EE) cnt[tid] = 0;
    __syncthreads();
    atomicAdd(&cnt[g_topidx[blockIdx.x*256 + tid]], 1);
    __syncthreads();
    if (tid < EE) g_ccnt[blockIdx.x][tid] = cnt[tid];
}

// global offsets: per-expert totals in parallel, short serial prefix
__global__ void build1_kernel()
{
    __shared__ int tot[EE];
    int tid = threadIdx.x;              // 64
    if (tid < EE) {
        int s = 0;
        #pragma unroll
        for (int c = 0; c < 32; c++) s += g_ccnt[c][tid];
        tot[tid] = s;
    }
    __syncthreads();
    if (tid == 0) {
        int s = 0;
        for (int e = 0; e < EE; e++) { g_off[e] = s; s += tot[e]; }
        g_off[EE] = s;
    }
}

// deterministic rank: base from earlier chunks + within-chunk scan (<=255 iters)
__global__ void build2b_kernel()
{
    __shared__ int sidx[256];
    int tid = threadIdx.x;              // 256, grid 32
    int b = blockIdx.x;
    int p = b*256 + tid;
    int e = g_topidx[p];
    sidx[tid] = e;
    __syncthreads();
    int base = g_off[e];
    for (int c = 0; c < 32; c++) base += (c < b) ? g_ccnt[c][e] : 0;
    int r = 0;
    for (int q = 0; q < tid; q++) r += (sidx[q] == e);
    int pos = base + r;
    g_tok[pos] = p >> 2;
    g_pos[p]   = pos;
}

// ============================ pipeline layout ============================
// A fp16: 4 stages x TM*80B.  B fp32 staging: 3 stages x 17408B (32 rows x 544B).
// B fp16: 2 regions x 8704B (32 rows x 272B).
#define B32_ST 17408
#define F16_ST 8704

// ============================ fused gate+up GEMM (fp32 weights) ============================
template<bool MOE, int TM>
__global__ void __launch_bounds__(256,2) gemm_gateup(const float* __restrict__ Wg,
                                                     const float* __restrict__ Wu)
{
    constexpr int K = HH;
    constexpr int N = MOE ? FF : SS;
    constexpr int NSLAB = K/32;
    constexpr int NPB = (TM==128) ? 2 : 1;
    constexpr int A_ST = TM*80;
    constexpr int B32_OF = 4*A_ST;
    constexpr int F16_OF = B32_OF + 3*B32_ST;

    extern __shared__ __align__(16) char dsm[];
    const uint32_t sb = smem_u32(dsm);

    const int tid = threadIdx.x, lane = tid & 31, w = tid >> 5;
    const int wm  = (TM==128) ? (w & 3)*32 : (w & 1)*32;
    const int wn2 = (TM==128) ? (w >> 2)*32 : (w >> 1)*16;

    int e = 0, off = 0, cnt = TT;
    if (MOE) { e = blockIdx.z; off = g_off[e]; cnt = g_off[e+1] - off; }
    int mb;
    if (TM == 128) {
        mb = blockIdx.y*128;
        if (MOE && mb + 128 > cnt) return;
    } else {
        mb = (cnt & ~127) + blockIdx.y*64;
        if (mb >= cnt) return;
    }
    const int nb = blockIdx.x*64;   // per-matrix column tile

    const float* Bg = MOE ? Wg + (size_t)e*HH*FF : Wg;
    const float* Bu = MOE ? Wu + (size_t)e*HH*FF : Wu;

    // ---- A fill (fp16 cp.async) ----
    const int aseg = tid & 3, ar0 = tid >> 2;
    const __half *pa0, *pa1 = nullptr;
    if (MOE) {
        int rc0 = (mb+ar0 < cnt) ? (mb+ar0) : (cnt-1);
        pa0 = g_xh + (size_t)g_tok[off+rc0]*HH + aseg*8;
        if (TM == 128) {
            int rc1 = (mb+ar0+64 < cnt) ? (mb+ar0+64) : (cnt-1);
            pa1 = g_xh + (size_t)g_tok[off+rc1]*HH + aseg*8;
        }
    } else {
        pa0 = g_xh + (size_t)(mb+ar0)*K + aseg*8;
        pa1 = g_xh + (size_t)(mb+ar0+64)*K + aseg*8;
    }
    const uint32_t dA0 = (uint32_t)(ar0*80 + aseg*16);
    const uint32_t dA1 = (uint32_t)((ar0+64)*80 + aseg*16);

    // ---- B fp32 fill: rb = warp row base, c16 = 16B col group ----
    const int rb = tid >> 5, c16 = tid & 31;
    const float* pBbase = (((c16 & 16) ? Bu : Bg) + nb + (c16 & 15)*4) + (size_t)rb*N;
    uint32_t dBB[4], dFF[4];
    #pragma unroll
    for (int k = 0; k < 4; k++) {
        dBB[k] = (uint32_t)((rb + 8*k)*544 + c16*16);
        dFF[k] = (uint32_t)((rb + 8*k)*272 + c16*8);
    }

    // ---- fragment addresses ----
    const int lr = lane & 15, lc = lane >> 4;
    const uint32_t aoff0 = (uint32_t)((wm + lr)*80 + lc*16);
    const uint32_t aoff1 = aoff0 + 16*80;
    uint32_t bG[NPB], bU[NPB];
    #pragma unroll
    for (int np = 0; np < NPB; np++) {
        bG[np] = (uint32_t)(lr*272 + (wn2 + np*16 + lc*8)*2);
        bU[np] = bG[np] + 128;
    }

    float accG[2][2*NPB][4] = {}, accU[2][2*NPB][4] = {};

    // ---- prologue: stages 0,1,2 (A + B fp32), one commit each ----
    #pragma unroll
    for (int s = 0; s < 3; s++) {
        uint32_t ab = sb + s*A_ST;
        CP16(ab + dA0, pa0 + s*32);
        if (TM == 128) CP16(ab + dA1, pa1 + s*32);
        uint32_t bbs = sb + B32_OF + s*B32_ST;
        #pragma unroll
        for (int k = 0; k < 4; k++) CP16(bbs + dBB[k], pBbase + (size_t)(8*k)*N + (size_t)s*32*N);
        CPCOMMIT();
    }

    for (int i = 0; i < NSLAB; i++) {
        CPWAIT2();          // stage i (A + B32) complete
        {
            const char* bsm = dsm + B32_OF + (i%3)*B32_ST;
            uint4 v0 = *(const uint4*)(bsm + dBB[0]);
            uint4 v1 = *(const uint4*)(bsm + dBB[1]);
            uint4 v2 = *(const uint4*)(bsm + dBB[2]);
            uint4 v3 = *(const uint4*)(bsm + dBB[3]);
            char* fsm = dsm + F16_OF + (i&1)*F16_ST;
            *(uint2*)(fsm + dFF[0]) = cvt4(v0);
            *(uint2*)(fsm + dFF[1]) = cvt4(v1);
            *(uint2*)(fsm + dFF[2]) = cvt4(v2);
            *(uint2*)(fsm + dFF[3]) = cvt4(v3);
        }
        __syncthreads();    // publish F16_i; all readers of reused regions done
        if (i + 3 < NSLAB) {
            uint32_t ab = sb + ((i+3)&3)*A_ST;
            CP16(ab + dA0, pa0 + (i+3)*32);
            if (TM == 128) CP16(ab + dA1, pa1 + (i+3)*32);
            uint32_t bbs = sb + B32_OF + ((i+3)%3)*B32_ST;
            #pragma unroll
            for (int k = 0; k < 4; k++) CP16(bbs + dBB[k], pBbase + (size_t)(8*k)*N + (size_t)(i+3)*32*N);
        }
        CPCOMMIT();         // unconditional: keeps group count aligned in tail
        const uint32_t ab = sb + (uint32_t)((i&3)*A_ST);
        const uint32_t fbm = sb + F16_OF + (uint32_t)((i&1)*F16_ST);
        #pragma unroll
        for (int ks = 0; ks < 2; ks++) {
            uint32_t a0[4], a1[4];
            ldsm4(a0, ab + aoff0 + ks*32);
            ldsm4(a1, ab + aoff1 + ks*32);
            #pragma unroll
            for (int np = 0; np < NPB; np++) {
                uint32_t gg[4], uu[4];
                ldsm4t(gg, fbm + bG[np] + ks*16*272);
                ldsm4t(uu, fbm + bU[np] + ks*16*272);
                mma_f16(accG[0][2*np],   a0, gg[0], gg[1]);
                mma_f16(accG[0][2*np+1], a0, gg[2], gg[3]);
                mma_f16(accG[1][2*np],   a1, gg[0], gg[1]);
                mma_f16(accG[1][2*np+1], a1, gg[2], gg[3]);
                mma_f16(accU[0][2*np],   a0, uu[0], uu[1]);
                mma_f16(accU[0][2*np+1], a0, uu[2], uu[3]);
                mma_f16(accU[1][2*np],   a1, uu[0], uu[1]);
                mma_f16(accU[1][2*np+1], a1, uu[2], uu[3]);
            }
        }
    }

    __half* dst = MOE ? g_hbuf16 : g_ybuf16;
    #pragma unroll
    for (int mt = 0; mt < 2; mt++) {
        const int rl0 = mb + wm + mt*16 + (lane >> 2);
        const int rl1 = rl0 + 8;
        const bool v0 = MOE ? (rl0 < cnt) : true;
        const bool v1 = MOE ? (rl1 < cnt) : true;
        const size_t row0 = MOE ? (size_t)(off + rl0) : (size_t)rl0;
        const size_t row1 = MOE ? (size_t)(off + rl1) : (size_t)rl1;
        #pragma unroll
        for (int nt = 0; nt < 2*NPB; nt++) {
            const int col = nb + wn2 + nt*8 + (lane & 3)*2;
            const float* g = accG[mt][nt];
            const float* u = accU[mt][nt];
            if (v0) *(__half2*)&dst[row0*N + col] =
                __floats2half2_rn(silu_f(g[0])*u[0], silu_f(g[1])*u[1]);
            if (v1) *(__half2*)&dst[row1*N + col] =
                __floats2half2_rn(silu_f(g[2])*u[2], silu_f(g[3])*u[3]);
        }
    }
}

// ============================ down GEMM (fp32 weights) ============================
template<bool MOE, int TM>
__global__ void __launch_bounds__(256,2) gemm_down(const float* __restrict__ Wd,
                                                   float* __restrict__ Cex)
{
    constexpr int K = MOE ? FF : SS;
    constexpr int N = HH;
    constexpr int NSLAB = K/32;
    constexpr int NPW = (TM==128) ? 4 : 2;
    constexpr int A_ST = TM*80;
    constexpr int B32_OF = 4*A_ST;
    constexpr int F16_OF = B32_OF + 3*B32_ST;

    extern __shared__ __align__(16) char dsm[];
    const uint32_t sb = smem_u32(dsm);

    const int tid = threadIdx.x, lane = tid & 31, w = tid >> 5;
    const int wm = (TM==128) ? (w & 3)*32 : (w & 1)*32;
    const int wn = (TM==128) ? (w >> 2)*64 : (w >> 1)*32;

    int e = 0, off = 0, cnt = TT;
    if (MOE) { e = blockIdx.z; off = g_off[e]; cnt = g_off[e+1] - off; }
    int mb;
    if (TM == 128) {
        mb = blockIdx.y*128;
        if (MOE && mb + 128 > cnt) return;
    } else {
        mb = (cnt & ~127) + blockIdx.y*64;
        if (mb >= cnt) return;
    }
    const int nb = blockIdx.x*128;

    const float* Bp = MOE ? Wd + (size_t)e*FF*HH : Wd;

    // ---- A fill ----
    const int aseg = tid & 3, ar0 = tid >> 2;
    const __half *pa0, *pa1 = nullptr;
    if (MOE) {
        int rc0 = (mb+ar0 < cnt) ? (mb+ar0) : (cnt-1);
        pa0 = g_hbuf16 + (size_t)(off+rc0)*FF + aseg*8;
        if (TM == 128) {
            int rc1 = (mb+ar0+64 < cnt) ? (mb+ar0+64) : (cnt-1);
            pa1 = g_hbuf16 + (size_t)(off+rc1)*FF + aseg*8;
        }
    } else {
        pa0 = g_ybuf16 + (size_t)(mb+ar0)*K + aseg*8;
        pa1 = g_ybuf16 + (size_t)(mb+ar0+64)*K + aseg*8;
    }
    const uint32_t dA0 = (uint32_t)(ar0*80 + aseg*16);
    const uint32_t dA1 = (uint32_t)((ar0+64)*80 + aseg*16);

    // ---- B fp32 fill ----
    const int rb = tid >> 5, c16 = tid & 31;
    const float* pBbase = (Bp + nb + c16*4) + (size_t)rb*N;
    uint32_t dBB[4], dFF[4];
    #pragma unroll
    for (int k = 0; k < 4; k++) {
        dBB[k] = (uint32_t)((rb + 8*k)*544 + c16*16);
        dFF[k] = (uint32_t)((rb + 8*k)*272 + c16*8);
    }

    // ---- fragment addresses ----
    const int lr = lane & 15, lc = lane >> 4;
    const uint32_t aoff0 = (uint32_t)((wm + lr)*80 + lc*16);
    const uint32_t aoff1 = aoff0 + 16*80;
    uint32_t boff[NPW];
    #pragma unroll
    for (int np = 0; np < NPW; np++)
        boff[np] = (uint32_t)(lr*272 + (wn + np*16 + lc*8)*2);

    float acc[2][2*NPW][4] = {};

    // ---- prologue ----
    #pragma unroll
    for (int s = 0; s < 3; s++) {
        uint32_t ab = sb + s*A_ST;
        CP16(ab + dA0, pa0 + s*32);
        if (TM == 128) CP16(ab + dA1, pa1 + s*32);
        uint32_t bbs = sb + B32_OF + s*B32_ST;
        #pragma unroll
        for (int k = 0; k < 4; k++) CP16(bbs + dBB[k], pBbase + (size_t)(8*k)*N + (size_t)s*32*N);
        CPCOMMIT();
    }

    for (int i = 0; i < NSLAB; i++) {
        CPWAIT2();
        {
            const char* bsm = dsm + B32_OF + (i%3)*B32_ST;
            uint4 v0 = *(const uint4*)(bsm + dBB[0]);
            uint4 v1 = *(const uint4*)(bsm + dBB[1]);
            uint4 v2 = *(const uint4*)(bsm + dBB[2]);
            uint4 v3 = *(const uint4*)(bsm + dBB[3]);
            char* fsm = dsm + F16_OF + (i&1)*F16_ST;
            *(uint2*)(fsm + dFF[0]) = cvt4(v0);
            *(uint2*)(fsm + dFF[1]) = cvt4(v1);
            *(uint2*)(fsm + dFF[2]) = cvt4(v2);
            *(uint2*)(fsm + dFF[3]) = cvt4(v3);
        }
        __syncthreads();
        if (i + 3 < NSLAB) {
            uint32_t ab = sb + ((i+3)&3)*A_ST;
            CP16(ab + dA0, pa0 + (i+3)*32);
            if (TM == 128) CP16(ab + dA1, pa1 + (i+3)*32);
            uint32_t bbs = sb + B32_OF + ((i+3)%3)*B32_ST;
            #pragma unroll
            for (int k = 0; k < 4; k++) CP16(bbs + dBB[k], pBbase + (size_t)(8*k)*N + (size_t)(i+3)*32*N);
        }
        CPCOMMIT();
        const uint32_t ab = sb + (uint32_t)((i&3)*A_ST);
        const uint32_t fbm = sb + F16_OF + (uint32_t)((i&1)*F16_ST);
        #pragma unroll
        for (int ks = 0; ks < 2; ks++) {
            uint32_t a0[4], a1[4];
            ldsm4(a0, ab + aoff0 + ks*32);
            ldsm4(a1, ab + aoff1 + ks*32);
            #pragma unroll
            for (int np = 0; np < NPW; np++) {
                uint32_t bbr[4];
                ldsm4t(bbr, fbm + boff[np] + ks*16*272);
                mma_f16(acc[0][2*np],   a0, bbr[0], bbr[1]);
                mma_f16(acc[0][2*np+1], a0, bbr[2], bbr[3]);
                mma_f16(acc[1][2*np],   a1, bbr[0], bbr[1]);
                mma_f16(acc[1][2*np+1], a1, bbr[2], bbr[3]);
            }
        }
    }

    #pragma unroll
    for (int mt = 0; mt < 2; mt++) {
        const int rl0 = mb + wm + mt*16 + (lane >> 2);
        const int rl1 = rl0 + 8;
        const bool v0 = MOE ? (rl0 < cnt) : true;
        const bool v1 = MOE ? (rl1 < cnt) : true;
        #pragma unroll
        for (int nt = 0; nt < 2*NPW; nt++) {
            const int col = nb + wn + nt*8 + (lane & 3)*2;
            const float* c = acc[mt][nt];
            if (!MOE) {
                float s0 = g_sig[rl0], s1 = g_sig[rl1];
                *(float2*)&Cex[(size_t)rl0*HH + col] = make_float2(s0*c[0], s0*c[1]);
                *(float2*)&Cex[(size_t)rl1*HH + col] = make_float2(s1*c[2], s1*c[3]);
            } else {
                if (v0) *(float2*)&g_pbuf[(size_t)(off+rl0)*HH + col] = make_float2(c[0], c[1]);
                if (v1) *(float2*)&g_pbuf[(size_t)(off+rl1)*HH + col] = make_float2(c[2], c[3]);
            }
        }
    }
}

// ============================ combine ============================
__global__ void combine_kernel(float* __restrict__ out)
{
    int t = blockIdx.x, tid = threadIdx.x;
    int p0 = g_pos[t*4+0], p1 = g_pos[t*4+1], p2 = g_pos[t*4+2], p3 = g_pos[t*4+3];
    float w0 = g_topw[t*4+0], w1 = g_topw[t*4+1], w2 = g_topw[t*4+2], w3 = g_topw[t*4+3];
    const float* r0 = g_pbuf + (size_t)p0*HH;
    const float* r1 = g_pbuf + (size_t)p1*HH;
    const float* r2 = g_pbuf + (size_t)p2*HH;
    const float* r3 = g_pbuf + (size_t)p3*HH;
    for (int c = tid; c < HH; c += 256) {
        float v = out[(size_t)t*HH + c];
        v = fmaf(w0, r0[c], v);
        v = fmaf(w1, r1[c], v);
        v = fmaf(w2, r2[c], v);
        v = fmaf(w3, r3[c], v);
        out[(size_t)t*HH + c] = v;
    }
}

// ============================ launch ============================
#define SM128 (4*(128*80) + 3*B32_ST + 2*F16_ST)   // 110592
#define SM64  (4*(64*80)  + 3*B32_ST + 2*F16_ST)   // 90112

extern "C" void kernel_launch(void* const* d_in, const int* in_sizes, int n_in,
                              void* d_out, int out_size)
{
    const float* x   = (const float*)d_in[0];
    const float* rw  = (const float*)d_in[1];
    const float* wg  = (const float*)d_in[2];
    const float* wu  = (const float*)d_in[3];
    const float* wd  = (const float*)d_in[4];
    const float* shg = (const float*)d_in[5];
    const float* shu = (const float*)d_in[6];
    const float* shd = (const float*)d_in[7];
    const float* seg = (const float*)d_in[8];
    float* out = (float*)d_out;
    (void)in_sizes; (void)n_in; (void)out_size;

    static bool init = false;
    if (!init) {
        init = true;
        cudaFuncSetAttribute(gemm_gateup<false,128>, cudaFuncAttributeMaxDynamicSharedMemorySize, SM128);
        cudaFuncSetAttribute(gemm_gateup<true,128>,  cudaFuncAttributeMaxDynamicSharedMemorySize, SM128);
        cudaFuncSetAttribute(gemm_gateup<true,64>,   cudaFuncAttributeMaxDynamicSharedMemorySize, SM64);
        cudaFuncSetAttribute(gemm_down<false,128>,   cudaFuncAttributeMaxDynamicSharedMemorySize, SM128);
        cudaFuncSetAttribute(gemm_down<true,128>,    cudaFuncAttributeMaxDynamicSharedMemorySize, SM128);
        cudaFuncSetAttribute(gemm_down<true,64>,     cudaFuncAttributeMaxDynamicSharedMemorySize, SM64);
    }

    // ---- routing (router also emits g_xh fp16) ----
    router_kernel<<<TT, 64>>>(x, rw, seg);
    build2a_kernel<<<32, 256>>>();
    build1_kernel<<<1, 64>>>();
    build2b_kernel<<<32, 256>>>();

    // ---- shared expert ----
    gemm_gateup<false,128><<<dim3(SS/64, TT/128), 256, SM128>>>(shg, shu);
    gemm_down<false,128><<<dim3(HH/128, TT/128), 256, SM128>>>(shd, out);

    // ---- MoE: full 128-row tiles + 64-row tails ----
    gemm_gateup<true,128><<<dim3(FF/64, TT/128, EE), 256, SM128>>>(wg, wu);
    gemm_gateup<true,64> <<<dim3(FF/64, 2, EE),      256, SM64 >>>(wg, wu);
    gemm_down<true,128><<<dim3(HH/128, TT/128, EE), 256, SM128>>>(wd, nullptr);
    gemm_down<true,64> <<<dim3(HH/128, 2, EE),      256, SM64 >>>(wd, nullptr);

    combine_kernel<<<TT, 256>>>(out);
}